// round 16
// baseline (speedup 1.0000x reference)
#include <cuda_runtime.h>
#include <cuda_fp16.h>
#include <cstdint>

// ===================== problem constants =====================
#define M_TOTAL 8192
#define N_TOTAL 4096
#define K_TOTAL 4096

#define BM 128
#define BN 256
#define BK 64
#define STAGES 3
#define NUM_KC (K_TOTAL / BK)   // 64
#define NTHREADS 256

#define A_BYTES (BM * 128)               // 16384 per (m-slab, kc) block
#define B_BYTES (BN * 128)               // 32768 per (n-tile, kc) block
#define STAGE_BYTES (A_BYTES + B_BYTES)  // 49152
#define MBAR_OFF (STAGES * STAGE_BYTES)  // 147456
#define SMEM_TOTAL (MBAR_OFF + 64)

// ===================== device scratch (blocked, pre-swizzled) =====================
// W_g: 16 n-tiles x 64 kc, each 32768B block; within block SW128(row*128 + chunk*16)
// X_g: 64 m-slabs x 64 kc, each 16384B block; same intra-block layout
__device__ __align__(128) unsigned char W_g[(size_t)N_TOTAL * K_TOTAL * 2];
__device__ __align__(128) unsigned char X_g[(size_t)M_TOTAL * K_TOTAL * 2];

// ===================== helpers =====================
#define DEVFN __device__ __forceinline__

DEVFN uint32_t smem_u32(const void* p) {
    uint32_t a;
    asm("{ .reg .u64 t; cvta.to.shared.u64 t, %1; cvt.u32.u64 %0, t; }" : "=r"(a) : "l"(p));
    return a;
}

#define SW128(o) ((o) ^ (((o) >> 3) & 0x70))

#define BAR_ARRIVE() asm volatile("bar.arrive 1, 512;" ::: "memory")
#define BAR_WAIT()   asm volatile("bar.sync 1, 512;" ::: "memory")

DEVFN void mbar_init(uint32_t a, uint32_t cnt) {
    asm volatile("mbarrier.init.shared.b64 [%0], %1;" :: "r"(a), "r"(cnt) : "memory");
}
DEVFN void mbar_expect(uint32_t a, uint32_t bytes) {
    asm volatile("mbarrier.arrive.expect_tx.shared.b64 _, [%0], %1;" :: "r"(a), "r"(bytes) : "memory");
}
DEVFN void mbar_wait(uint32_t a, uint32_t ph) {
    asm volatile(
        "{\n\t.reg .pred P;\n\t"
        "WL%=:\n\t"
        "mbarrier.try_wait.parity.acquire.cta.shared::cta.b64 P, [%0], %1;\n\t"
        "@!P bra WL%=;\n\t}"
        :: "r"(a), "r"(ph) : "memory");
}
DEVFN void bulk_g2s(uint32_t dst, const void* src, uint32_t bytes, uint32_t mb) {
    asm volatile(
        "cp.async.bulk.shared::cta.global.mbarrier::complete_tx::bytes [%0], [%1], %2, [%3];"
        :: "r"(dst), "l"(src), "r"(bytes), "r"(mb) : "memory");
}
#define FENCE_PROXY_ASYNC() asm volatile("fence.proxy.async.shared::cta;" ::: "memory")

DEVFN void ldsm4(uint32_t* r, uint32_t addr) {
    asm volatile("ldmatrix.sync.aligned.m8n8.x4.shared.b16 {%0,%1,%2,%3}, [%4];"
                 : "=r"(r[0]), "=r"(r[1]), "=r"(r[2]), "=r"(r[3]) : "r"(addr));
}

DEVFN void mma16816(float* d, const uint32_t* a, const uint32_t* b) {
    asm("mma.sync.aligned.m16n8k16.row.col.f32.f16.f16.f32 "
        "{%0,%1,%2,%3}, {%4,%5,%6,%7}, {%8,%9}, {%0,%1,%2,%3};"
        : "+f"(d[0]), "+f"(d[1]), "+f"(d[2]), "+f"(d[3])
        : "r"(a[0]), "r"(a[1]), "r"(a[2]), "r"(a[3]), "r"(b[0]), "r"(b[1]));
}

// E2M1 magnitudes * 2 = {0,1,2,3,4,6,8,12} packed as nibbles of 0xC8643210.
DEVFN __half2 dec2(int b, float hs) {  // hs = 0.5f * scale
    int ch = (b >> 4) & 7, sh = (b >> 7) & 1;
    int cl = b & 7,        sl = (b >> 3) & 1;
    float mh = (float)((0xC8643210u >> (ch * 4)) & 0xF);
    float ml = (float)((0xC8643210u >> (cl * 4)) & 0xF);
    float fh = mh * (sh ? -hs : hs);
    float fl = ml * (sl ? -hs : hs);
    return make_half2(__float2half_rn(fh), __float2half_rn(fl));
}

#define W_BLOCKS (N_TOTAL * K_TOTAL / 2 / 4 / 256)   // 8192
#define X_BLOCKS (M_TOTAL * K_TOTAL / 8 / 256)       // 16384

// ===================== prep: dequant W + convert X into blocked layout =====================
__global__ void __launch_bounds__(256)
prep_kernel(const int* __restrict__ wp, const float* __restrict__ ws,
            const float* __restrict__ x) {
    const int bid = blockIdx.x;
    if (bid < W_BLOCKS) {
        int i = bid * 256 + threadIdx.x;             // int4 group: 4 packed bytes -> 8 halves (16B)
        int4 p = reinterpret_cast<const int4*>(wp)[i];
        float hs = __ldg(ws + (i >> 1)) * 0.5f;
        union { __half2 h[4]; uint4 u; } o;
        o.h[0] = dec2(p.x & 255, hs);
        o.h[1] = dec2(p.y & 255, hs);
        o.h[2] = dec2(p.z & 255, hs);
        o.h[3] = dec2(p.w & 255, hs);
        int h0 = i << 3;
        int n = h0 >> 12, k = h0 & 4095;
        int tn = n >> 8, lr = n & 255;
        int kc = k >> 6, c = (k & 63) >> 3;
        size_t dst = (size_t)((tn << 6) + kc) * B_BYTES + SW128((uint32_t)(lr * 128 + c * 16));
        *reinterpret_cast<uint4*>(W_g + dst) = o.u;
    } else {
        int i = (bid - W_BLOCKS) * 256 + threadIdx.x;  // 8 floats -> 8 halves (16B)
        float4 v0 = reinterpret_cast<const float4*>(x)[2 * i];
        float4 v1 = reinterpret_cast<const float4*>(x)[2 * i + 1];
        union { __half2 h[4]; uint4 u; } o;
        o.h[0] = make_half2(__float2half_rn(v0.x), __float2half_rn(v0.y));
        o.h[1] = make_half2(__float2half_rn(v0.z), __float2half_rn(v0.w));
        o.h[2] = make_half2(__float2half_rn(v1.x), __float2half_rn(v1.y));
        o.h[3] = make_half2(__float2half_rn(v1.z), __float2half_rn(v1.w));
        int h0 = i << 3;
        int m = h0 >> 12, k = h0 & 4095;
        int tm = m >> 7, lr = m & 127;
        int kc = k >> 6, c = (k & 63) >> 3;
        size_t dst = (size_t)((tm << 6) + kc) * A_BYTES + SW128((uint32_t)(lr * 128 + c * 16));
        *reinterpret_cast<uint4*>(X_g + dst) = o.u;
    }
}

// ===================== HMMA GEMM: bulk-copy pipeline, rotating verifier =====================
__global__ void __launch_bounds__(NTHREADS, 1)
gemm_kernel(const float* __restrict__ bias, float* __restrict__ out) {
    extern __shared__ char smem[];
    const uint32_t sb = smem_u32(smem);
    const uint32_t mb0 = sb + MBAR_OFF;
    const int tid = threadIdx.x;
    const int wid = tid >> 5;
    const int lane = tid & 31;
    const int tn = blockIdx.x;          // n-tile 0..15
    const int tm = blockIdx.y;          // m-slab 0..63
    const unsigned char* Ablk = X_g + (size_t)(tm * 64) * A_BYTES;
    const unsigned char* Bblk = W_g + (size_t)(tn * 64) * B_BYTES;

    const int warp_m = wid & 1;
    const int warp_n = wid >> 1;

    float acc[4][8][4];
#pragma unroll
    for (int i = 0; i < 4; i++)
#pragma unroll
        for (int j = 0; j < 8; j++)
#pragma unroll
            for (int k = 0; k < 4; k++) acc[i][j][k] = 0.f;

    const int a_row = warp_m * 64 + (lane & 15);
    const int a_ch  = lane >> 4;
    const int b_row = warp_n * 64 + ((lane >> 4) & 1) * 8 + (lane & 7);
    const int b_ch  = (lane >> 3) & 1;

    uint32_t afr[2][4][4];
    uint32_t bfr[2][8][2];

#define LD_AFRAGS(buf, base, ks_) do { \
    _Pragma("unroll") \
    for (int mt = 0; mt < 4; mt++) { \
        uint32_t off = (uint32_t)((a_row + mt * 16) * 128 + (2 * (ks_) + a_ch) * 16); \
        ldsm4(afr[buf][mt], (base) + SW128(off)); \
    } } while (0)

#define LD_BFRAGS(buf, base, ks_) do { \
    _Pragma("unroll") \
    for (int ng = 0; ng < 4; ng++) { \
        uint32_t r_[4]; \
        uint32_t off = (uint32_t)((b_row + ng * 16) * 128 + (2 * (ks_) + b_ch) * 16); \
        ldsm4(r_, (base) + SW128(off)); \
        bfr[buf][2 * ng][0] = r_[0]; bfr[buf][2 * ng][1] = r_[1]; \
        bfr[buf][2 * ng + 1][0] = r_[2]; bfr[buf][2 * ng + 1][1] = r_[3]; \
    } } while (0)

#define MMA_BATCH(buf) do { \
    _Pragma("unroll") \
    for (int mt = 0; mt < 4; mt++) \
        _Pragma("unroll") \
        for (int nt = 0; nt < 8; nt++) \
            mma16816(acc[mt][nt], afr[buf][mt], bfr[buf][nt]); \
    } while (0)

    // single-thread bulk issue of stage `st` into slot st%3
#define ISSUE_BULK(st_) do { \
    int _s = (st_); \
    if (tid == 0 && _s < NUM_KC) { \
        uint32_t _slot = (uint32_t)(_s % STAGES); \
        uint32_t _mb = mb0 + _slot * 8; \
        uint32_t _d = sb + _slot * STAGE_BYTES; \
        FENCE_PROXY_ASYNC(); \
        mbar_expect(_mb, STAGE_BYTES); \
        bulk_g2s(_d, Ablk + (size_t)_s * A_BYTES, A_BYTES, _mb); \
        bulk_g2s(_d + A_BYTES, Bblk + (size_t)_s * B_BYTES, B_BYTES, _mb); \
    } } while (0)

    // init mbarriers
    if (tid == 0) {
#pragma unroll
        for (int s = 0; s < STAGES; s++) mbar_init(mb0 + s * 8, 1);
        FENCE_PROXY_ASYNC();
    }
    __syncthreads();

    // prologue: stages 0,1; all threads wait full[0]; warm ks0 frags
    ISSUE_BULK(0);
    ISSUE_BULK(1);
    mbar_wait(mb0 + 0, 0);
    LD_AFRAGS(0, sb, 0);
    LD_BFRAGS(0, sb + A_BYTES, 0);

    for (int kc = 0; kc < NUM_KC; kc++) {
        const uint32_t abase = sb + (uint32_t)(kc % STAGES) * STAGE_BYTES;
        const uint32_t bbase = abase + A_BYTES;
        const uint32_t anext = sb + (uint32_t)((kc + 1) % STAGES) * STAGE_BYTES;
        const uint32_t bnext = anext + A_BYTES;

        // ks0: issue stage kc+2 (slot freed by prev-iter BAR_WAIT)
        ISSUE_BULK(kc + 2);
        LD_AFRAGS(1, abase, 1);
        LD_BFRAGS(1, bbase, 1);
        MMA_BATCH(0);

        // ks1
        LD_AFRAGS(0, abase, 2);
        LD_BFRAGS(0, bbase, 2);
        MMA_BATCH(1);

        // ks2: last reads of stage kc. ONLY the rotating verifier warp ((kc+1)&7)
        // polls full[kc+1]; its post-wait BAR_ARRIVE gates BAR_WAIT's release, so
        // the named barrier (smem-fencing) carries data-ready to the other warps.
        LD_AFRAGS(1, abase, 3);
        LD_BFRAGS(1, bbase, 3);
        if (kc + 1 < NUM_KC && wid == ((kc + 1) & 7))
            mbar_wait(mb0 + ((kc + 1) % STAGES) * 8, (uint32_t)(((kc + 1) / STAGES) & 1));
        BAR_ARRIVE();
        MMA_BATCH(0);

        // ks3: WAIT (slot kc fully read + stage kc+1 verified), prefetch next frags
        BAR_WAIT();
        if (kc + 1 < NUM_KC) {
            LD_AFRAGS(0, anext, 0);
            LD_BFRAGS(0, bnext, 0);
        }
        MMA_BATCH(1);
    }

    // ===================== epilogue =====================
    const int m0 = tm * BM;
    const int n0 = tn * BN;
    const int mrow = m0 + warp_m * 64 + (lane >> 2);
    const int ncol = n0 + warp_n * 64 + (lane & 3) * 2;

    float2 bv[8];
#pragma unroll
    for (int nt = 0; nt < 8; nt++) {
        bv[nt].x = __ldg(bias + ncol + nt * 8);
        bv[nt].y = __ldg(bias + ncol + nt * 8 + 1);
    }

#pragma unroll
    for (int mt = 0; mt < 4; mt++) {
        float* r0 = out + (size_t)(mrow + mt * 16) * N_TOTAL + ncol;
        float* r1 = r0 + 8 * N_TOTAL;
#pragma unroll
        for (int nt = 0; nt < 8; nt++) {
            float2 v0 = make_float2(acc[mt][nt][0] + bv[nt].x, acc[mt][nt][1] + bv[nt].y);
            float2 v1 = make_float2(acc[mt][nt][2] + bv[nt].x, acc[mt][nt][3] + bv[nt].y);
            *reinterpret_cast<float2*>(r0 + nt * 8) = v0;
            *reinterpret_cast<float2*>(r1 + nt * 8) = v1;
        }
    }
}

// ===================== launch =====================
extern "C" void kernel_launch(void* const* d_in, const int* in_sizes, int n_in,
                              void* d_out, int out_size) {
    const float* x    = (const float*)d_in[0];
    const int*   wp   = (const int*)d_in[1];
    const float* ws   = (const float*)d_in[2];
    const float* bias = (const float*)d_in[3];
    float* out = (float*)d_out;

    cudaFuncSetAttribute(gemm_kernel, cudaFuncAttributeMaxDynamicSharedMemorySize, SMEM_TOTAL);

    prep_kernel<<<W_BLOCKS + X_BLOCKS, 256>>>(wp, ws, x);

    dim3 grid(N_TOTAL / BN, M_TOTAL / BM);  // (16, 64)
    gemm_kernel<<<grid, NTHREADS, SMEM_TOTAL>>>(bias, out);
}

// round 17
// speedup vs baseline: 1.5151x; 1.5151x over previous
#include <cuda_runtime.h>
#include <cuda_fp16.h>
#include <cstdint>

// ===================== problem constants =====================
#define M_TOTAL 8192
#define N_TOTAL 4096
#define K_TOTAL 4096

#define BM 128
#define BN 256
#define BK 64
#define STAGES 3
#define NUM_KC (K_TOTAL / BK)   // 64
#define NTHREADS 256

#define A_BYTES (BM * 128)               // 16384 per (m-slab, kc) block
#define B_BYTES (BN * 128)               // 32768 per (n-tile, kc) block
#define STAGE_BYTES (A_BYTES + B_BYTES)  // 49152
#define MBAR_OFF (STAGES * STAGE_BYTES)  // 147456
#define SMEM_TOTAL (MBAR_OFF + 64)

// ===================== device scratch (blocked, pre-swizzled) =====================
// W_g: 16 n-tiles x 64 kc, each 32768B block; within block SW128(row*128 + chunk*16)
// X_g: 64 m-slabs x 64 kc, each 16384B block; same intra-block layout
__device__ __align__(128) unsigned char W_g[(size_t)N_TOTAL * K_TOTAL * 2];
__device__ __align__(128) unsigned char X_g[(size_t)M_TOTAL * K_TOTAL * 2];

// ===================== helpers =====================
#define DEVFN __device__ __forceinline__

DEVFN uint32_t smem_u32(const void* p) {
    uint32_t a;
    asm("{ .reg .u64 t; cvta.to.shared.u64 t, %1; cvt.u32.u64 %0, t; }" : "=r"(a) : "l"(p));
    return a;
}

#define SW128(o) ((o) ^ (((o) >> 3) & 0x70))

#define BAR_ARRIVE() asm volatile("bar.arrive 1, 512;" ::: "memory")
#define BAR_WAIT()   asm volatile("bar.sync 1, 512;" ::: "memory")

DEVFN void mbar_init(uint32_t a, uint32_t cnt) {
    asm volatile("mbarrier.init.shared.b64 [%0], %1;" :: "r"(a), "r"(cnt) : "memory");
}
DEVFN void mbar_expect(uint32_t a, uint32_t bytes) {
    asm volatile("mbarrier.arrive.expect_tx.shared.b64 _, [%0], %1;" :: "r"(a), "r"(bytes) : "memory");
}
DEVFN void mbar_wait(uint32_t a, uint32_t ph) {
    asm volatile(
        "{\n\t.reg .pred P;\n\t"
        "WL%=:\n\t"
        "mbarrier.try_wait.parity.shared.b64 P, [%0], %1;\n\t"
        "@!P bra WL%=;\n\t}"
        :: "r"(a), "r"(ph) : "memory");
}
DEVFN void bulk_g2s(uint32_t dst, const void* src, uint32_t bytes, uint32_t mb) {
    asm volatile(
        "cp.async.bulk.shared::cta.global.mbarrier::complete_tx::bytes [%0], [%1], %2, [%3];"
        :: "r"(dst), "l"(src), "r"(bytes), "r"(mb) : "memory");
}
#define FENCE_PROXY_ASYNC() asm volatile("fence.proxy.async.shared::cta;" ::: "memory")

DEVFN void ldsm4(uint32_t* r, uint32_t addr) {
    asm volatile("ldmatrix.sync.aligned.m8n8.x4.shared.b16 {%0,%1,%2,%3}, [%4];"
                 : "=r"(r[0]), "=r"(r[1]), "=r"(r[2]), "=r"(r[3]) : "r"(addr));
}

DEVFN void mma16816(float* d, const uint32_t* a, const uint32_t* b) {
    asm("mma.sync.aligned.m16n8k16.row.col.f32.f16.f16.f32 "
        "{%0,%1,%2,%3}, {%4,%5,%6,%7}, {%8,%9}, {%0,%1,%2,%3};"
        : "+f"(d[0]), "+f"(d[1]), "+f"(d[2]), "+f"(d[3])
        : "r"(a[0]), "r"(a[1]), "r"(a[2]), "r"(a[3]), "r"(b[0]), "r"(b[1]));
}

// E2M1 magnitudes * 2 = {0,1,2,3,4,6,8,12} packed as nibbles of 0xC8643210.
DEVFN __half2 dec2(int b, float hs) {  // hs = 0.5f * scale
    int ch = (b >> 4) & 7, sh = (b >> 7) & 1;
    int cl = b & 7,        sl = (b >> 3) & 1;
    float mh = (float)((0xC8643210u >> (ch * 4)) & 0xF);
    float ml = (float)((0xC8643210u >> (cl * 4)) & 0xF);
    float fh = mh * (sh ? -hs : hs);
    float fl = ml * (sl ? -hs : hs);
    return make_half2(__float2half_rn(fh), __float2half_rn(fl));
}

#define W_BLOCKS (N_TOTAL * K_TOTAL / 2 / 4 / 256)   // 8192
#define X_BLOCKS (M_TOTAL * K_TOTAL / 8 / 256)       // 16384

// ===================== prep: dequant W + convert X into blocked layout =====================
__global__ void __launch_bounds__(256)
prep_kernel(const int* __restrict__ wp, const float* __restrict__ ws,
            const float* __restrict__ x) {
    const int bid = blockIdx.x;
    if (bid < W_BLOCKS) {
        int i = bid * 256 + threadIdx.x;             // int4 group: 4 packed bytes -> 8 halves (16B)
        int4 p = reinterpret_cast<const int4*>(wp)[i];
        float hs = __ldg(ws + (i >> 1)) * 0.5f;
        union { __half2 h[4]; uint4 u; } o;
        o.h[0] = dec2(p.x & 255, hs);
        o.h[1] = dec2(p.y & 255, hs);
        o.h[2] = dec2(p.z & 255, hs);
        o.h[3] = dec2(p.w & 255, hs);
        int h0 = i << 3;
        int n = h0 >> 12, k = h0 & 4095;
        int tn = n >> 8, lr = n & 255;
        int kc = k >> 6, c = (k & 63) >> 3;
        size_t dst = (size_t)((tn << 6) + kc) * B_BYTES + SW128((uint32_t)(lr * 128 + c * 16));
        *reinterpret_cast<uint4*>(W_g + dst) = o.u;
    } else {
        int i = (bid - W_BLOCKS) * 256 + threadIdx.x;  // 8 floats -> 8 halves (16B)
        float4 v0 = reinterpret_cast<const float4*>(x)[2 * i];
        float4 v1 = reinterpret_cast<const float4*>(x)[2 * i + 1];
        union { __half2 h[4]; uint4 u; } o;
        o.h[0] = make_half2(__float2half_rn(v0.x), __float2half_rn(v0.y));
        o.h[1] = make_half2(__float2half_rn(v0.z), __float2half_rn(v0.w));
        o.h[2] = make_half2(__float2half_rn(v1.x), __float2half_rn(v1.y));
        o.h[3] = make_half2(__float2half_rn(v1.z), __float2half_rn(v1.w));
        int h0 = i << 3;
        int m = h0 >> 12, k = h0 & 4095;
        int tm = m >> 7, lr = m & 127;
        int kc = k >> 6, c = (k & 63) >> 3;
        size_t dst = (size_t)((tm << 6) + kc) * A_BYTES + SW128((uint32_t)(lr * 128 + c * 16));
        *reinterpret_cast<uint4*>(X_g + dst) = o.u;
    }
}

// ===================== HMMA GEMM with bulk-copy pipeline =====================
__global__ void __launch_bounds__(NTHREADS, 1)
gemm_kernel(const float* __restrict__ bias, float* __restrict__ out) {
    extern __shared__ char smem[];
    const uint32_t sb = smem_u32(smem);
    const uint32_t mb0 = sb + MBAR_OFF;
    const int tid = threadIdx.x;
    const int wid = tid >> 5;
    const int lane = tid & 31;
    const int tn = blockIdx.x;          // n-tile 0..15
    const int tm = blockIdx.y;          // m-slab 0..63
    const unsigned char* Ablk = X_g + (size_t)(tm * 64) * A_BYTES;
    const unsigned char* Bblk = W_g + (size_t)(tn * 64) * B_BYTES;

    const int warp_m = wid & 1;
    const int warp_n = wid >> 1;

    float acc[4][8][4];
#pragma unroll
    for (int i = 0; i < 4; i++)
#pragma unroll
        for (int j = 0; j < 8; j++)
#pragma unroll
            for (int k = 0; k < 4; k++) acc[i][j][k] = 0.f;

    const int a_row = warp_m * 64 + (lane & 15);
    const int a_ch  = lane >> 4;
    const int b_row = warp_n * 64 + ((lane >> 4) & 1) * 8 + (lane & 7);
    const int b_ch  = (lane >> 3) & 1;

    uint32_t afr[2][4][4];
    uint32_t bfr[2][8][2];

#define LD_AFRAGS(buf, base, ks_) do { \
    _Pragma("unroll") \
    for (int mt = 0; mt < 4; mt++) { \
        uint32_t off = (uint32_t)((a_row + mt * 16) * 128 + (2 * (ks_) + a_ch) * 16); \
        ldsm4(afr[buf][mt], (base) + SW128(off)); \
    } } while (0)

#define LD_BFRAGS(buf, base, ks_) do { \
    _Pragma("unroll") \
    for (int ng = 0; ng < 4; ng++) { \
        uint32_t r_[4]; \
        uint32_t off = (uint32_t)((b_row + ng * 16) * 128 + (2 * (ks_) + b_ch) * 16); \
        ldsm4(r_, (base) + SW128(off)); \
        bfr[buf][2 * ng][0] = r_[0]; bfr[buf][2 * ng][1] = r_[1]; \
        bfr[buf][2 * ng + 1][0] = r_[2]; bfr[buf][2 * ng + 1][1] = r_[3]; \
    } } while (0)

#define MMA_BATCH(buf) do { \
    _Pragma("unroll") \
    for (int mt = 0; mt < 4; mt++) \
        _Pragma("unroll") \
        for (int nt = 0; nt < 8; nt++) \
            mma16816(acc[mt][nt], afr[buf][mt], bfr[buf][nt]); \
    } while (0)

    // single-thread bulk issue of stage `st` into slot st%3
#define ISSUE_BULK(st_) do { \
    int _s = (st_); \
    if (tid == 0 && _s < NUM_KC) { \
        uint32_t _slot = (uint32_t)(_s % STAGES); \
        uint32_t _mb = mb0 + _slot * 8; \
        uint32_t _d = sb + _slot * STAGE_BYTES; \
        FENCE_PROXY_ASYNC(); \
        mbar_expect(_mb, STAGE_BYTES); \
        bulk_g2s(_d, Ablk + (size_t)_s * A_BYTES, A_BYTES, _mb); \
        bulk_g2s(_d + A_BYTES, Bblk + (size_t)_s * B_BYTES, B_BYTES, _mb); \
    } } while (0)

    // init mbarriers
    if (tid == 0) {
#pragma unroll
        for (int s = 0; s < STAGES; s++) mbar_init(mb0 + s * 8, 1);
        FENCE_PROXY_ASYNC();
    }
    __syncthreads();

    // prologue: stages 0,1; all threads wait full[0]; warm ks0 frags
    ISSUE_BULK(0);
    ISSUE_BULK(1);
    mbar_wait(mb0 + 0, 0);
    LD_AFRAGS(0, sb, 0);
    LD_BFRAGS(0, sb + A_BYTES, 0);

    for (int kc = 0; kc < NUM_KC; kc++) {
        const uint32_t abase = sb + (uint32_t)(kc % STAGES) * STAGE_BYTES;
        const uint32_t bbase = abase + A_BYTES;
        const uint32_t anext = sb + (uint32_t)((kc + 1) % STAGES) * STAGE_BYTES;
        const uint32_t bnext = anext + A_BYTES;

        // ks0: issue stage kc+2 (slot freed by prev-iter BAR_WAIT)
        ISSUE_BULK(kc + 2);
        LD_AFRAGS(1, abase, 1);
        LD_BFRAGS(1, bbase, 1);
        MMA_BATCH(0);

        // ks1
        LD_AFRAGS(0, abase, 2);
        LD_BFRAGS(0, bbase, 2);
        MMA_BATCH(1);

        // ks2: last reads of stage kc -> all threads poll mbar for stage kc+1 -> ARRIVE
        LD_AFRAGS(1, abase, 3);
        LD_BFRAGS(1, bbase, 3);
        if (kc + 1 < NUM_KC)
            mbar_wait(mb0 + ((kc + 1) % STAGES) * 8, (uint32_t)(((kc + 1) / STAGES) & 1));
        BAR_ARRIVE();
        MMA_BATCH(0);

        // ks3: WAIT (slot kc fully read by all), prefetch next stage ks0 frags
        BAR_WAIT();
        if (kc + 1 < NUM_KC) {
            LD_AFRAGS(0, anext, 0);
            LD_BFRAGS(0, bnext, 0);
        }
        MMA_BATCH(1);
    }

    // ===================== epilogue =====================
    const int m0 = tm * BM;
    const int n0 = tn * BN;
    const int mrow = m0 + warp_m * 64 + (lane >> 2);
    const int ncol = n0 + warp_n * 64 + (lane & 3) * 2;

    float2 bv[8];
#pragma unroll
    for (int nt = 0; nt < 8; nt++) {
        bv[nt].x = __ldg(bias + ncol + nt * 8);
        bv[nt].y = __ldg(bias + ncol + nt * 8 + 1);
    }

#pragma unroll
    for (int mt = 0; mt < 4; mt++) {
        float* r0 = out + (size_t)(mrow + mt * 16) * N_TOTAL + ncol;
        float* r1 = r0 + 8 * N_TOTAL;
#pragma unroll
        for (int nt = 0; nt < 8; nt++) {
            float2 v0 = make_float2(acc[mt][nt][0] + bv[nt].x, acc[mt][nt][1] + bv[nt].y);
            float2 v1 = make_float2(acc[mt][nt][2] + bv[nt].x, acc[mt][nt][3] + bv[nt].y);
            *reinterpret_cast<float2*>(r0 + nt * 8) = v0;
            *reinterpret_cast<float2*>(r1 + nt * 8) = v1;
        }
    }
}

// ===================== launch =====================
extern "C" void kernel_launch(void* const* d_in, const int* in_sizes, int n_in,
                              void* d_out, int out_size) {
    const float* x    = (const float*)d_in[0];
    const int*   wp   = (const int*)d_in[1];
    const float* ws   = (const float*)d_in[2];
    const float* bias = (const float*)d_in[3];
    float* out = (float*)d_out;

    cudaFuncSetAttribute(gemm_kernel, cudaFuncAttributeMaxDynamicSharedMemorySize, SMEM_TOTAL);

    prep_kernel<<<W_BLOCKS + X_BLOCKS, 256>>>(wp, ws, x);

    dim3 grid(N_TOTAL / BN, M_TOTAL / BM);  // (16, 64)
    gemm_kernel<<<grid, NTHREADS, SMEM_TOTAL>>>(bias, out);
}